// round 14
// baseline (speedup 1.0000x reference)
#include <cuda_runtime.h>
#include <cstdint>

// ============================================================================
// EdgeModel round 14: R12 base (best: 1613us) + free pipeline-depth bumps:
//  - gemm1_bulk: N-split 2 CTAs/tile (2 CTAs/SM), A ring depth 3 (was 2).
//  - gemm23: A2 ring depth 4 inside the A3 region (free SMEM), split A/B
//    empty barriers.
//  - gather_kernel: unchanged (at DRAM floor).
// ============================================================================

#if defined(__CUDA_ARCH_FEAT_SM103_ALL) || defined(__CUDA_ARCH_FEAT_SM100_ALL) || \
    defined(__CUDA_ARCH_FEAT_SM101_ALL) || defined(__CUDA_ARCH_SPECIFIC__)   || \
    defined(__CUDA_ARCH_FAMILY_SPECIFIC__)
#define TC_OK 1
#else
#define TC_OK 0
#endif

#define E_MAX  500000
#define TMAX   3907

__device__ uint32_t g_xi [(size_t)TMAX * 16 * 4096];   // gathered X image
__device__ uint32_t g_h1i[(size_t)TMAX * 16 * 4096];   // h1 image
__device__ uint32_t g_w1i[512 * 512];
__device__ uint32_t g_w2i[512 * 512];
__device__ uint32_t g_w3i[512 * 128];

// ---------------------------------------------------------------------------
#define SWZ(x) ((x) ^ (((x) >> 3) & 0x70))

__device__ __forceinline__ uint32_t f2tf32(float x) {
    uint32_t r; asm("cvt.rna.tf32.f32 %0, %1;" : "=r"(r) : "f"(x)); return r;
}
__device__ __forceinline__ uint32_t smem_u32(const void* p) {
    uint32_t a;
    asm("{ .reg .u64 t; cvta.to.shared.u64 t, %1; cvt.u32.u64 %0, t; }"
        : "=r"(a) : "l"(p));
    return a;
}
__device__ __forceinline__ uint32_t elect1() {
    uint32_t p;
    asm volatile("{ .reg .pred p; elect.sync _|p, 0xFFFFFFFF; selp.b32 %0,1,0,p; }"
                 : "=r"(p));
    return p;
}

static constexpr uint64_t DESC_BASE =
    (2ull << 61) | (1ull << 46) | (64ull << 32) | (1ull << 16);
__device__ __forceinline__ uint64_t mkdesc(uint32_t smem_addr) {
    return DESC_BASE | ((uint64_t)(smem_addr >> 4) & 0x3FFF);
}

static constexpr uint32_t IDESC_TF32 =
    (1u << 4) | (2u << 7) | (2u << 10) | ((128u / 8) << 17) | ((128u / 16) << 24);

__device__ __forceinline__ void mma_tf32_ss(uint32_t d_tmem, uint64_t a_desc,
                                            uint64_t b_desc, bool acc) {
#if TC_OK
    uint32_t en = acc ? 1u : 0u;
    asm volatile(
        "{\n\t"
        ".reg .pred p;\n\t"
        "setp.ne.u32 p, %4, 0;\n\t"
        "tcgen05.mma.cta_group::1.kind::tf32 [%0], %1, %2, %3, {%5,%5,%5,%5}, p;\n\t"
        "}"
        :: "r"(d_tmem), "l"(a_desc), "l"(b_desc), "r"(IDESC_TF32),
           "r"(en), "r"(0u)
        : "memory");
#endif
}

__device__ __forceinline__ void tc_alloc(uint32_t addr, uint32_t ncols) {
#if TC_OK
    asm volatile("tcgen05.alloc.cta_group::1.sync.aligned.shared::cta.b32 [%0], %1;"
                 :: "r"(addr), "r"(ncols) : "memory");
    asm volatile("tcgen05.relinquish_alloc_permit.cta_group::1.sync.aligned;");
#endif
}
__device__ __forceinline__ void tc_dealloc(uint32_t tmem, uint32_t ncols) {
#if TC_OK
    asm volatile("tcgen05.dealloc.cta_group::1.sync.aligned.b32 %0, %1;"
                 :: "r"(tmem), "r"(ncols));
#endif
}
__device__ __forceinline__ void tc_commit(uint32_t mbar) {
#if TC_OK
    asm volatile("tcgen05.commit.cta_group::1.mbarrier::arrive::one.shared::cluster.b64 [%0];"
                 :: "r"(mbar) : "memory");
#endif
}
__device__ __forceinline__ void tc_wait_ld() {
#if TC_OK
    asm volatile("tcgen05.wait::ld.sync.aligned;" ::: "memory");
#endif
}
__device__ __forceinline__ void tc_fence_after() {
#if TC_OK
    asm volatile("tcgen05.fence::after_thread_sync;" ::: "memory");
#endif
}
__device__ __forceinline__ void fence_async_shared() {
    asm volatile("fence.proxy.async.shared::cta;" ::: "memory");
}
__device__ __forceinline__ void mbar_init(uint32_t addr, uint32_t cnt) {
    asm volatile("mbarrier.init.shared.b64 [%0], %1;" :: "r"(addr), "r"(cnt) : "memory");
}
__device__ __forceinline__ void mbar_expect_tx(uint32_t addr, uint32_t bytes) {
    asm volatile("mbarrier.arrive.expect_tx.shared.b64 _, [%0], %1;"
                 :: "r"(addr), "r"(bytes) : "memory");
}
__device__ __forceinline__ void mbar_wait(uint32_t addr, uint32_t parity) {
    asm volatile(
        "{\n\t"
        ".reg .pred P;\n\t"
        "WL_%=:\n\t"
        "mbarrier.try_wait.parity.acquire.cta.shared::cta.b64 P, [%0], %1, 0x989680;\n\t"
        "@P bra WD_%=;\n\t"
        "bra WL_%=;\n\t"
        "WD_%=:\n\t"
        "}"
        :: "r"(addr), "r"(parity) : "memory");
}
__device__ __forceinline__ void bulk_g2s(uint32_t dst, const void* src,
                                         uint32_t bytes, uint32_t mbar) {
    asm volatile("cp.async.bulk.shared::cta.global.mbarrier::complete_tx::bytes "
                 "[%0], [%1], %2, [%3];"
                 :: "r"(dst), "l"(src), "r"(bytes), "r"(mbar) : "memory");
}

__device__ __forceinline__ void ldtm_x32(uint32_t* r, uint32_t addr) {
#if TC_OK
    asm volatile(
        "tcgen05.ld.sync.aligned.32x32b.x32.b32 "
        "{%0,%1,%2,%3,%4,%5,%6,%7,%8,%9,%10,%11,%12,%13,%14,%15,"
        "%16,%17,%18,%19,%20,%21,%22,%23,%24,%25,%26,%27,%28,%29,%30,%31}, [%32];"
        : "=r"(r[0]),  "=r"(r[1]),  "=r"(r[2]),  "=r"(r[3]),
          "=r"(r[4]),  "=r"(r[5]),  "=r"(r[6]),  "=r"(r[7]),
          "=r"(r[8]),  "=r"(r[9]),  "=r"(r[10]), "=r"(r[11]),
          "=r"(r[12]), "=r"(r[13]), "=r"(r[14]), "=r"(r[15]),
          "=r"(r[16]), "=r"(r[17]), "=r"(r[18]), "=r"(r[19]),
          "=r"(r[20]), "=r"(r[21]), "=r"(r[22]), "=r"(r[23]),
          "=r"(r[24]), "=r"(r[25]), "=r"(r[26]), "=r"(r[27]),
          "=r"(r[28]), "=r"(r[29]), "=r"(r[30]), "=r"(r[31])
        : "r"(addr));
#endif
}

// ---------------------------------------------------------------------------
__global__ void prep_weights(const float* __restrict__ W,
                             uint32_t* __restrict__ img, int N) {
    int i = blockIdx.x * blockDim.x + threadIdx.x;
    if (i >= 512 * N) return;
    int k = i / N, n = i % N;
    int nt = n >> 7, kc = k >> 5, nin = n & 127, kin = k & 31;
    img[(size_t)(nt * 16 + kc) * 4096 + (SWZ(nin * 128 + kin * 4) >> 2)] =
        f2tf32(W[i]);
}

// ---------------------------------------------------------------------------
// Gather: block (tile, kc) writes one 16KB swizzled tf32 X-image chunk.
// ---------------------------------------------------------------------------
__global__ __launch_bounds__(256)
void gather_kernel(const float* __restrict__ src, const float* __restrict__ dstv,
                   const float* __restrict__ eat, const float* __restrict__ u,
                   const int* __restrict__ batch,
                   uint32_t* __restrict__ ximg, int M)
{
    __shared__ int s_batch[128];
    const int tid  = threadIdx.x;
    const int tile = blockIdx.x;
    const int kc   = blockIdx.y;
    const int row0 = tile * 128;

    if (tid < 128) {
        int grow = row0 + tid;
        s_batch[tid] = (grow < M) ? batch[grow] : 0;
    }
    __syncthreads();

    uint32_t* blk = ximg + ((size_t)tile * 16 + kc) * 4096;

    #pragma unroll
    for (int i = 0; i < 4; i++) {
        int slot = tid + i * 256;
        int r    = slot >> 3;
        int c4   = (slot & 7) << 2;
        int grow = row0 + r;
        int gk   = kc * 32 + c4;
        float4 v = make_float4(0.f, 0.f, 0.f, 0.f);
        if (gk >= 384) {
            v = *reinterpret_cast<const float4*>(
                u + (size_t)s_batch[r] * 128 + (gk - 384));
        } else if (grow < M) {
            const float* p;
            if (gk < 128)      p = src  + (size_t)grow * 128 + gk;
            else if (gk < 256) p = dstv + (size_t)grow * 128 + (gk - 128);
            else               p = eat  + (size_t)grow * 128 + (gk - 256);
            v = *reinterpret_cast<const float4*>(p);
        }
        uint4 t;
        t.x = f2tf32(v.x); t.y = f2tf32(v.y);
        t.z = f2tf32(v.z); t.w = f2tf32(v.w);
        *reinterpret_cast<uint4*>(blk + (SWZ(r * 128 + c4 * 4) >> 2)) = t;
    }
}

// ---------------------------------------------------------------------------
// GEMM1 (bulk-fed, N-split 2 CTAs per tile, 2 CTAs/SM):
// CTA(tile, half) computes D1[128, 256] for h1 cols [half*256, +256).
// A ring 3x16KB @ [0,48K), B ring 2x32KB @ [48K,112K). 113KB/CTA.
// ---------------------------------------------------------------------------
__global__ __launch_bounds__(256, 2)
void gemm1_bulk(const uint32_t* __restrict__ ximg,
                const uint32_t* __restrict__ w1img,
                const float* __restrict__ b1,
                uint32_t* __restrict__ h1img, int M)
{
#if TC_OK
    extern __shared__ char dynraw[];
    __shared__ uint32_t s_tptr[1];
    __shared__ alignas(8) uint64_t s_bars[11];
    // 0-2:fA[3] 3-5:eA[3] 6-7:fB[2] 8-9:eB[2] 10:mbF

    const int tid  = threadIdx.x;
    const int warp = tid >> 5;
    const int lane = tid & 31;
    const int tile = blockIdx.x;
    const int half = blockIdx.y;

    uint32_t dbase = (smem_u32(dynraw) + 1023u) & ~1023u;
    const uint32_t abase = dbase;                 // A ring 3x16KB
    const uint32_t bbase = dbase + 49152;         // B ring 2x32KB

    if (warp == 0) tc_alloc(smem_u32(s_tptr), 256);
    if (tid == 0) {
        for (int i = 0; i < 11; i++) mbar_init(smem_u32(&s_bars[i]), 1);
    }
    __syncthreads();
    const uint32_t tmem = s_tptr[0];
    uint32_t fA[3], eA[3], fB[2], eB[2];
    #pragma unroll
    for (int i = 0; i < 3; i++) { fA[i] = smem_u32(&s_bars[i]); eA[i] = smem_u32(&s_bars[3 + i]); }
    #pragma unroll
    for (int i = 0; i < 2; i++) { fB[i] = smem_u32(&s_bars[6 + i]); eB[i] = smem_u32(&s_bars[8 + i]); }
    const uint32_t mbF = smem_u32(&s_bars[10]);

    if (warp == 1) {
        // ---- producer: A image (16KB, ring 3) + half's B (32KB, ring 2) ----
        if (elect1()) {
            uint32_t peA[3] = {0, 0, 0}, peB[2] = {0, 0};
            for (int kc = 0; kc < 16; kc++) {
                const int j = kc % 3, b = kc & 1;
                if (kc >= 3) { mbar_wait(eA[j], peA[j] & 1); peA[j]++; }
                mbar_expect_tx(fA[j], 16384);
                bulk_g2s(abase + j * 16384,
                         ximg + ((size_t)tile * 16 + kc) * 4096, 16384, fA[j]);
                if (kc >= 2) { mbar_wait(eB[b], peB[b] & 1); peB[b]++; }
                mbar_expect_tx(fB[b], 32768);
                #pragma unroll
                for (int l = 0; l < 2; l++) {
                    int nt = half * 2 + l;
                    bulk_g2s(bbase + b * 32768 + l * 16384,
                             w1img + (size_t)(nt * 16 + kc) * 4096, 16384, fB[b]);
                }
            }
        }
    } else if (warp == 0) {
        // ---- MMA issuer: 2 n-tiles x 4 k8 per chunk ----
        if (elect1()) {
            uint32_t cfA[3] = {0, 0, 0};
            for (int kc = 0; kc < 16; kc++) {
                const int j = kc % 3, b = kc & 1;
                mbar_wait(fA[j], cfA[j] & 1); cfA[j]++;
                mbar_wait(fB[b], (kc >> 1) & 1);
                uint64_t ad = mkdesc(abase + j * 16384);
                #pragma unroll
                for (int l = 0; l < 2; l++) {
                    uint64_t bd = mkdesc(bbase + b * 32768 + l * 16384);
                    #pragma unroll
                    for (int ks = 0; ks < 4; ks++)
                        mma_tf32_ss(tmem + l * 128, ad + ks * 2, bd + ks * 2,
                                    !(kc == 0 && ks == 0));
                }
                tc_commit(eA[j]);
                tc_commit(eB[b]);
                if (kc == 15) tc_commit(mbF);
            }
        }
    }

    // ---- epilogue: D1[128,256] + b1, relu, cvt, swizzled h1 chunks ----
    mbar_wait(mbF, 0);
    tc_fence_after();
    {
        const int sp  = warp & 3;
        const int r   = sp * 32 + lane;
        const int cb0 = (warp >> 2) * 128;      // local col base (0 or 128)
        #pragma unroll
        for (int g = 0; g < 4; g++) {
            const int col  = cb0 + g * 32;      // local col in [0,256)
            const int gcol = half * 256 + col;  // global h1 col
            uint32_t regs[32];
            ldtm_x32(regs, tmem + col);
            tc_wait_ld();
            uint32_t* blk = h1img + ((size_t)tile * 16 + (gcol >> 5)) * 4096;
            #pragma unroll
            for (int q = 0; q < 8; q++) {
                float4 bv = *reinterpret_cast<const float4*>(b1 + gcol + q * 4);
                uint4 t;
                t.x = f2tf32(fmaxf(__uint_as_float(regs[q*4+0]) + bv.x, 0.f));
                t.y = f2tf32(fmaxf(__uint_as_float(regs[q*4+1]) + bv.y, 0.f));
                t.z = f2tf32(fmaxf(__uint_as_float(regs[q*4+2]) + bv.z, 0.f));
                t.w = f2tf32(fmaxf(__uint_as_float(regs[q*4+3]) + bv.w, 0.f));
                *reinterpret_cast<uint4*>(blk + (SWZ(r * 128 + q * 16) >> 2)) = t;
            }
        }
    }
    __syncthreads();
    if (warp == 0) tc_dealloc(tmem, 256);
#endif
}

// ---------------------------------------------------------------------------
// GEMM2+3 fused: A2 ring depth 4 (lives in the 64KB A3 region, free),
// split A/B empty barriers. Otherwise identical to R9/R12.
// ---------------------------------------------------------------------------
__global__ __launch_bounds__(384)
void gemm23_kernel(const uint32_t* __restrict__ h1img,
                   const uint32_t* __restrict__ w2img,
                   const float* __restrict__ b2,
                   const uint32_t* __restrict__ w3img,
                   const float* __restrict__ bs3,
                   float* __restrict__ out, int M)
{
#if TC_OK
    extern __shared__ char dynraw[];
    __shared__ uint32_t s_tptr[1];
    __shared__ alignas(8) uint64_t s_bars[17];
    // 0-3:fA[4] 4-7:eA[4] 8-9:fB[2] 10-11:eB[2] 12:mbF2
    // 13-14:fB3[2] 15:eG3 16:mbF3

    const int tid  = threadIdx.x;
    const int warp = tid >> 5;
    const int lane = tid & 31;
    const int tile = blockIdx.x;
    const int row0 = tile * 128;

    uint32_t dbase = (smem_u32(dynraw) + 1023u) & ~1023u;
    char* dyn = dynraw + (dbase - smem_u32(dynraw));
    const uint32_t abase = dbase;                 // A2 ring 4x16KB / A3 4x16KB
    const uint32_t bbase = dbase + 65536;         // B2 ring 2x64KB / B3 ring 2x64KB

    if (warp == 0) tc_alloc(smem_u32(s_tptr), 512);
    if (tid == 0) {
        for (int i = 0; i < 17; i++) mbar_init(smem_u32(&s_bars[i]), 1);
    }
    __syncthreads();
    const uint32_t tmem = s_tptr[0];
    uint32_t fA[4], eA[4];
    #pragma unroll
    for (int i = 0; i < 4; i++) { fA[i] = smem_u32(&s_bars[i]); eA[i] = smem_u32(&s_bars[4 + i]); }
    const uint32_t fB[2]  = { smem_u32(&s_bars[8]),  smem_u32(&s_bars[9])  };
    const uint32_t eB[2]  = { smem_u32(&s_bars[10]), smem_u32(&s_bars[11]) };
    const uint32_t mbF2   = smem_u32(&s_bars[12]);
    const uint32_t fB3[2] = { smem_u32(&s_bars[13]), smem_u32(&s_bars[14]) };
    const uint32_t eG3    = smem_u32(&s_bars[15]);
    const uint32_t mbF3   = smem_u32(&s_bars[16]);

    if (warp == 8) {
        if (elect1()) {
            uint32_t peA[4] = {0, 0, 0, 0}, peB[2] = {0, 0};
            for (int kc = 0; kc < 16; kc++) {
                const int j = kc & 3, b = kc & 1;
                if (kc >= 4) { mbar_wait(eA[j], peA[j] & 1); peA[j]++; }
                mbar_expect_tx(fA[j], 16384);
                bulk_g2s(abase + j * 16384,
                         h1img + ((size_t)tile * 16 + kc) * 4096, 16384, fA[j]);
                if (kc >= 2) { mbar_wait(eB[b], peB[b] & 1); peB[b]++; }
                mbar_expect_tx(fB[b], 65536);
                #pragma unroll
                for (int nt = 0; nt < 4; nt++)
                    bulk_g2s(bbase + b * 65536 + nt * 16384,
                             w2img + (size_t)(nt * 16 + kc) * 4096, 16384, fB[b]);
            }
            mbar_wait(mbF2, 0);
            int phg = 0;
            for (int g = 0; g < 4; g++) {
                const int s = g & 1;
                if (g >= 2) { mbar_wait(eG3, phg & 1); phg++; }
                mbar_expect_tx(fB3[s], 65536);
                bulk_g2s(bbase + s * 65536, w3img + (size_t)g * 16384, 65536, fB3[s]);
            }
        }
    }

    if (warp == 0) {
        if (elect1()) {
            uint32_t cfA[4] = {0, 0, 0, 0};
            for (int kc = 0; kc < 16; kc++) {
                const int j = kc & 3, b = kc & 1;
                mbar_wait(fA[j], cfA[j] & 1); cfA[j]++;
                mbar_wait(fB[b], (kc >> 1) & 1);
                uint64_t ad = mkdesc(abase + j * 16384);
                #pragma unroll
                for (int nt = 0; nt < 4; nt++) {
                    uint64_t bd = mkdesc(bbase + b * 65536 + nt * 16384);
                    #pragma unroll
                    for (int ks = 0; ks < 4; ks++)
                        mma_tf32_ss(tmem + nt * 128, ad + ks * 2, bd + ks * 2,
                                    !(kc == 0 && ks == 0));
                }
                tc_commit(eA[j]);
                tc_commit(eB[b]);
                if (kc == 15) tc_commit(mbF2);
            }
        }
    }

    if (warp < 8) {
        mbar_wait(mbF2, 0);
        tc_fence_after();
        const int r  = (warp & 3) * 32 + lane;
        const int jh = (warp >> 2) * 2;
        int phb3[2] = {0, 0};
        for (int g = 0; g < 4; g++) {
            if (g >= 1) mbar_wait(eG3, (g - 1) & 1);
            #pragma unroll
            for (int jj = 0; jj < 2; jj++) {
                const int j = jh + jj;
                uint32_t regs[32];
                ldtm_x32(regs, tmem + g * 128 + j * 32);
                tc_wait_ld();
                const int colb = g * 128 + j * 32;
                #pragma unroll
                for (int q = 0; q < 8; q++) {
                    float4 bv = *reinterpret_cast<const float4*>(b2 + colb + q * 4);
                    uint4 t;
                    t.x = f2tf32(fmaxf(__uint_as_float(regs[q*4+0]) + bv.x, 0.f));
                    t.y = f2tf32(fmaxf(__uint_as_float(regs[q*4+1]) + bv.y, 0.f));
                    t.z = f2tf32(fmaxf(__uint_as_float(regs[q*4+2]) + bv.z, 0.f));
                    t.w = f2tf32(fmaxf(__uint_as_float(regs[q*4+3]) + bv.w, 0.f));
                    *reinterpret_cast<uint4*>(
                        dyn + j * 16384 + SWZ(r * 128 + q * 16)) = t;
                }
            }
            fence_async_shared();
            asm volatile("bar.sync 1, 256;" ::: "memory");
            if (warp == 0 && elect1()) {
                const int s = g & 1;
                mbar_wait(fB3[s], phb3[s] & 1); phb3[s]++;
                #pragma unroll
                for (int j = 0; j < 4; j++) {
                    uint64_t ad = mkdesc(abase + j * 16384);
                    uint64_t bd = mkdesc(bbase + s * 65536 + j * 16384);
                    #pragma unroll
                    for (int ks = 0; ks < 4; ks++)
                        mma_tf32_ss(tmem, ad + ks * 2, bd + ks * 2,
                                    !(g == 0 && j == 0 && ks == 0));
                }
                tc_commit(g == 3 ? mbF3 : eG3);
            }
        }
    }

    mbar_wait(mbF3, 0);
    tc_fence_after();
    if (warp < 8) {
        const int sp  = warp & 3;
        const int row = row0 + sp * 32 + lane;
        const int cb0 = (warp >> 2) * 64;
        #pragma unroll
        for (int gg = 0; gg < 2; gg++) {
            const int col = cb0 + gg * 32;
            uint32_t regs[32];
            ldtm_x32(regs, tmem + col);
            tc_wait_ld();
            if (row < M) {
                #pragma unroll
                for (int q = 0; q < 8; q++) {
                    float4 bv = *reinterpret_cast<const float4*>(bs3 + col + q * 4);
                    float4 o;
                    o.x = __uint_as_float(regs[q*4+0]) + bv.x;
                    o.y = __uint_as_float(regs[q*4+1]) + bv.y;
                    o.z = __uint_as_float(regs[q*4+2]) + bv.z;
                    o.w = __uint_as_float(regs[q*4+3]) + bv.w;
                    *reinterpret_cast<float4*>(out + (size_t)row * 128 + col + q * 4) = o;
                }
            }
        }
    }
    __syncthreads();
    if (warp == 0) tc_dealloc(tmem, 512);
#endif
}

// ---------------------------------------------------------------------------
extern "C" void kernel_launch(void* const* d_in, const int* in_sizes, int n_in,
                              void* d_out, int out_size)
{
    const float* src   = (const float*)d_in[0];
    const float* dstv  = (const float*)d_in[1];
    const float* eat   = (const float*)d_in[2];
    const float* u     = (const float*)d_in[3];
    const int*   batch = (const int*)  d_in[4];
    const float* W1    = (const float*)d_in[5];
    const float* b1    = (const float*)d_in[6];
    const float* W2    = (const float*)d_in[7];
    const float* b2    = (const float*)d_in[8];
    const float* W3    = (const float*)d_in[9];
    const float* b3    = (const float*)d_in[10];
    float*       out   = (float*)d_out;

    const int M = in_sizes[4];

    uint32_t *xi, *h1i, *w1i, *w2i, *w3i;
    cudaGetSymbolAddress((void**)&xi,  g_xi);
    cudaGetSymbolAddress((void**)&h1i, g_h1i);
    cudaGetSymbolAddress((void**)&w1i, g_w1i);
    cudaGetSymbolAddress((void**)&w2i, g_w2i);
    cudaGetSymbolAddress((void**)&w3i, g_w3i);

    static bool attr_done = false;
    if (!attr_done) {
        // gemm1: A 3x16K + B 2x32K = 112K + 1K pad = 115712; 2/SM = 231424 <= 232448
        cudaFuncSetAttribute(gemm1_bulk,
            cudaFuncAttributeMaxDynamicSharedMemorySize, 115712);
        cudaFuncSetAttribute(gemm23_kernel,
            cudaFuncAttributeMaxDynamicSharedMemorySize, 197632);
        attr_done = true;
    }

    prep_weights<<<(512 * 512 + 255) / 256, 256>>>(W1, w1i, 512);
    prep_weights<<<(512 * 512 + 255) / 256, 256>>>(W2, w2i, 512);
    prep_weights<<<(512 * 128 + 255) / 256, 256>>>(W3, w3i, 128);

    const int tiles = (M + 127) / 128;

    dim3 gg(tiles, 16);
    gather_kernel<<<gg, 256>>>(src, dstv, eat, u, batch, xi, M);

    dim3 g1(tiles, 2);
    gemm1_bulk<<<g1, 256, 115712>>>(xi, w1i, b1, h1i, M);

    gemm23_kernel<<<tiles, 384, 197632>>>(h1i, w2i, b2, w3i, b3, out, M);
}

// round 15
// speedup vs baseline: 1.0698x; 1.0698x over previous
#include <cuda_runtime.h>
#include <cstdint>

// ============================================================================
// EdgeModel round 15 == round 12 (best verified: 1613us). Locked-in optimum:
//  - gather_kernel: standalone gather/concat -> swizzled tf32 X image
//    (280us @ 79% DRAM = at traffic floor).
//  - gemm1_bulk: bulk-fed tcgen05 TF32, N-split across 2 CTAs per tile
//    (256 TMEM cols each -> 2 CTAs/SM latency hiding).
//  - gemm23: fused layers 2+3, single pipeline, D2 512 cols in TMEM,
//    GEMM3 accumulates into cols [0,128) from evacuated A3 images.
// Rounds 13/14 (M-fattening, deeper rings) and 5/10/11 (clusters/multicast)
// all regressed; this configuration is the measured optimum.
// ============================================================================

#if defined(__CUDA_ARCH_FEAT_SM103_ALL) || defined(__CUDA_ARCH_FEAT_SM100_ALL) || \
    defined(__CUDA_ARCH_FEAT_SM101_ALL) || defined(__CUDA_ARCH_SPECIFIC__)   || \
    defined(__CUDA_ARCH_FAMILY_SPECIFIC__)
#define TC_OK 1
#else
#define TC_OK 0
#endif

#define E_MAX  500000
#define TMAX   3907

__device__ uint32_t g_xi [(size_t)TMAX * 16 * 4096];   // gathered X image
__device__ uint32_t g_h1i[(size_t)TMAX * 16 * 4096];   // h1 image
__device__ uint32_t g_w1i[512 * 512];
__device__ uint32_t g_w2i[512 * 512];
__device__ uint32_t g_w3i[512 * 128];

// ---------------------------------------------------------------------------
#define SWZ(x) ((x) ^ (((x) >> 3) & 0x70))

__device__ __forceinline__ uint32_t f2tf32(float x) {
    uint32_t r; asm("cvt.rna.tf32.f32 %0, %1;" : "=r"(r) : "f"(x)); return r;
}
__device__ __forceinline__ uint32_t smem_u32(const void* p) {
    uint32_t a;
    asm("{ .reg .u64 t; cvta.to.shared.u64 t, %1; cvt.u32.u64 %0, t; }"
        : "=r"(a) : "l"(p));
    return a;
}
__device__ __forceinline__ uint32_t elect1() {
    uint32_t p;
    asm volatile("{ .reg .pred p; elect.sync _|p, 0xFFFFFFFF; selp.b32 %0,1,0,p; }"
                 : "=r"(p));
    return p;
}

static constexpr uint64_t DESC_BASE =
    (2ull << 61) | (1ull << 46) | (64ull << 32) | (1ull << 16);
__device__ __forceinline__ uint64_t mkdesc(uint32_t smem_addr) {
    return DESC_BASE | ((uint64_t)(smem_addr >> 4) & 0x3FFF);
}

static constexpr uint32_t IDESC_TF32 =
    (1u << 4) | (2u << 7) | (2u << 10) | ((128u / 8) << 17) | ((128u / 16) << 24);

__device__ __forceinline__ void mma_tf32_ss(uint32_t d_tmem, uint64_t a_desc,
                                            uint64_t b_desc, bool acc) {
#if TC_OK
    uint32_t en = acc ? 1u : 0u;
    asm volatile(
        "{\n\t"
        ".reg .pred p;\n\t"
        "setp.ne.u32 p, %4, 0;\n\t"
        "tcgen05.mma.cta_group::1.kind::tf32 [%0], %1, %2, %3, {%5,%5,%5,%5}, p;\n\t"
        "}"
        :: "r"(d_tmem), "l"(a_desc), "l"(b_desc), "r"(IDESC_TF32),
           "r"(en), "r"(0u)
        : "memory");
#endif
}

__device__ __forceinline__ void tc_alloc(uint32_t addr, uint32_t ncols) {
#if TC_OK
    asm volatile("tcgen05.alloc.cta_group::1.sync.aligned.shared::cta.b32 [%0], %1;"
                 :: "r"(addr), "r"(ncols) : "memory");
    asm volatile("tcgen05.relinquish_alloc_permit.cta_group::1.sync.aligned;");
#endif
}
__device__ __forceinline__ void tc_dealloc(uint32_t tmem, uint32_t ncols) {
#if TC_OK
    asm volatile("tcgen05.dealloc.cta_group::1.sync.aligned.b32 %0, %1;"
                 :: "r"(tmem), "r"(ncols));
#endif
}
__device__ __forceinline__ void tc_commit(uint32_t mbar) {
#if TC_OK
    asm volatile("tcgen05.commit.cta_group::1.mbarrier::arrive::one.shared::cluster.b64 [%0];"
                 :: "r"(mbar) : "memory");
#endif
}
__device__ __forceinline__ void tc_wait_ld() {
#if TC_OK
    asm volatile("tcgen05.wait::ld.sync.aligned;" ::: "memory");
#endif
}
__device__ __forceinline__ void tc_fence_after() {
#if TC_OK
    asm volatile("tcgen05.fence::after_thread_sync;" ::: "memory");
#endif
}
__device__ __forceinline__ void fence_async_shared() {
    asm volatile("fence.proxy.async.shared::cta;" ::: "memory");
}
__device__ __forceinline__ void mbar_init(uint32_t addr, uint32_t cnt) {
    asm volatile("mbarrier.init.shared.b64 [%0], %1;" :: "r"(addr), "r"(cnt) : "memory");
}
__device__ __forceinline__ void mbar_expect_tx(uint32_t addr, uint32_t bytes) {
    asm volatile("mbarrier.arrive.expect_tx.shared.b64 _, [%0], %1;"
                 :: "r"(addr), "r"(bytes) : "memory");
}
__device__ __forceinline__ void mbar_wait(uint32_t addr, uint32_t parity) {
    asm volatile(
        "{\n\t"
        ".reg .pred P;\n\t"
        "WL_%=:\n\t"
        "mbarrier.try_wait.parity.acquire.cta.shared::cta.b64 P, [%0], %1, 0x989680;\n\t"
        "@P bra WD_%=;\n\t"
        "bra WL_%=;\n\t"
        "WD_%=:\n\t"
        "}"
        :: "r"(addr), "r"(parity) : "memory");
}
__device__ __forceinline__ void bulk_g2s(uint32_t dst, const void* src,
                                         uint32_t bytes, uint32_t mbar) {
    asm volatile("cp.async.bulk.shared::cta.global.mbarrier::complete_tx::bytes "
                 "[%0], [%1], %2, [%3];"
                 :: "r"(dst), "l"(src), "r"(bytes), "r"(mbar) : "memory");
}

__device__ __forceinline__ void ldtm_x32(uint32_t* r, uint32_t addr) {
#if TC_OK
    asm volatile(
        "tcgen05.ld.sync.aligned.32x32b.x32.b32 "
        "{%0,%1,%2,%3,%4,%5,%6,%7,%8,%9,%10,%11,%12,%13,%14,%15,"
        "%16,%17,%18,%19,%20,%21,%22,%23,%24,%25,%26,%27,%28,%29,%30,%31}, [%32];"
        : "=r"(r[0]),  "=r"(r[1]),  "=r"(r[2]),  "=r"(r[3]),
          "=r"(r[4]),  "=r"(r[5]),  "=r"(r[6]),  "=r"(r[7]),
          "=r"(r[8]),  "=r"(r[9]),  "=r"(r[10]), "=r"(r[11]),
          "=r"(r[12]), "=r"(r[13]), "=r"(r[14]), "=r"(r[15]),
          "=r"(r[16]), "=r"(r[17]), "=r"(r[18]), "=r"(r[19]),
          "=r"(r[20]), "=r"(r[21]), "=r"(r[22]), "=r"(r[23]),
          "=r"(r[24]), "=r"(r[25]), "=r"(r[26]), "=r"(r[27]),
          "=r"(r[28]), "=r"(r[29]), "=r"(r[30]), "=r"(r[31])
        : "r"(addr));
#endif
}

// ---------------------------------------------------------------------------
__global__ void prep_weights(const float* __restrict__ W,
                             uint32_t* __restrict__ img, int N) {
    int i = blockIdx.x * blockDim.x + threadIdx.x;
    if (i >= 512 * N) return;
    int k = i / N, n = i % N;
    int nt = n >> 7, kc = k >> 5, nin = n & 127, kin = k & 31;
    img[(size_t)(nt * 16 + kc) * 4096 + (SWZ(nin * 128 + kin * 4) >> 2)] =
        f2tf32(W[i]);
}

// ---------------------------------------------------------------------------
// Gather: block (tile, kc) writes one 16KB swizzled tf32 X-image chunk.
// ---------------------------------------------------------------------------
__global__ __launch_bounds__(256)
void gather_kernel(const float* __restrict__ src, const float* __restrict__ dstv,
                   const float* __restrict__ eat, const float* __restrict__ u,
                   const int* __restrict__ batch,
                   uint32_t* __restrict__ ximg, int M)
{
    __shared__ int s_batch[128];
    const int tid  = threadIdx.x;
    const int tile = blockIdx.x;
    const int kc   = blockIdx.y;
    const int row0 = tile * 128;

    if (tid < 128) {
        int grow = row0 + tid;
        s_batch[tid] = (grow < M) ? batch[grow] : 0;
    }
    __syncthreads();

    uint32_t* blk = ximg + ((size_t)tile * 16 + kc) * 4096;

    #pragma unroll
    for (int i = 0; i < 4; i++) {
        int slot = tid + i * 256;
        int r    = slot >> 3;
        int c4   = (slot & 7) << 2;
        int grow = row0 + r;
        int gk   = kc * 32 + c4;
        float4 v = make_float4(0.f, 0.f, 0.f, 0.f);
        if (gk >= 384) {
            v = *reinterpret_cast<const float4*>(
                u + (size_t)s_batch[r] * 128 + (gk - 384));
        } else if (grow < M) {
            const float* p;
            if (gk < 128)      p = src  + (size_t)grow * 128 + gk;
            else if (gk < 256) p = dstv + (size_t)grow * 128 + (gk - 128);
            else               p = eat  + (size_t)grow * 128 + (gk - 256);
            v = *reinterpret_cast<const float4*>(p);
        }
        uint4 t;
        t.x = f2tf32(v.x); t.y = f2tf32(v.y);
        t.z = f2tf32(v.z); t.w = f2tf32(v.w);
        *reinterpret_cast<uint4*>(blk + (SWZ(r * 128 + c4 * 4) >> 2)) = t;
    }
}

// ---------------------------------------------------------------------------
// GEMM1 (bulk-fed, N-split 2 CTAs per tile): CTA(tile, half) computes
// D1[128, 256] for h1 cols [half*256, half*256+256), 256 TMEM cols.
// 256 threads: warp0 MMA | warp1 producer | 8 warps epilogue.
// A ring 2x16KB @ [0,32K), B ring 2x32KB @ [32K,96K). 2 CTAs/SM.
// ---------------------------------------------------------------------------
__global__ __launch_bounds__(256, 2)
void gemm1_bulk(const uint32_t* __restrict__ ximg,
                const uint32_t* __restrict__ w1img,
                const float* __restrict__ b1,
                uint32_t* __restrict__ h1img, int M)
{
#if TC_OK
    extern __shared__ char dynraw[];
    __shared__ uint32_t s_tptr[1];
    __shared__ alignas(8) uint64_t s_bars[7];
    // 0:fA0 1:fA1 2:fB0 3:fB1 4:eAB0 5:eAB1 6:mbF

    const int tid  = threadIdx.x;
    const int warp = tid >> 5;
    const int lane = tid & 31;
    const int tile = blockIdx.x;
    const int half = blockIdx.y;

    uint32_t dbase = (smem_u32(dynraw) + 1023u) & ~1023u;
    const uint32_t abase = dbase;                 // A ring 2x16KB
    const uint32_t bbase = dbase + 32768;         // B ring 2x32KB

    if (warp == 0) tc_alloc(smem_u32(s_tptr), 256);
    if (tid == 0) {
        for (int i = 0; i < 7; i++) mbar_init(smem_u32(&s_bars[i]), 1);
    }
    __syncthreads();
    const uint32_t tmem = s_tptr[0];
    const uint32_t fA[2]  = { smem_u32(&s_bars[0]), smem_u32(&s_bars[1]) };
    const uint32_t fB[2]  = { smem_u32(&s_bars[2]), smem_u32(&s_bars[3]) };
    const uint32_t eAB[2] = { smem_u32(&s_bars[4]), smem_u32(&s_bars[5]) };
    const uint32_t mbF    = smem_u32(&s_bars[6]);

    if (warp == 1) {
        // ---- producer: A image (16KB) + this half's B (2x16KB) per chunk ----
        if (elect1()) {
            int ph[2] = {0, 0};
            for (int kc = 0; kc < 16; kc++) {
                const int b = kc & 1;
                if (kc >= 2) { mbar_wait(eAB[b], ph[b] & 1); ph[b]++; }
                mbar_expect_tx(fA[b], 16384);
                bulk_g2s(abase + b * 16384,
                         ximg + ((size_t)tile * 16 + kc) * 4096, 16384, fA[b]);
                mbar_expect_tx(fB[b], 32768);
                #pragma unroll
                for (int l = 0; l < 2; l++) {
                    int nt = half * 2 + l;
                    bulk_g2s(bbase + b * 32768 + l * 16384,
                             w1img + (size_t)(nt * 16 + kc) * 4096, 16384, fB[b]);
                }
            }
        }
    } else if (warp == 0) {
        // ---- MMA issuer: 2 n-tiles x 4 k8 per chunk ----
        if (elect1()) {
            int phA[2] = {0, 0}, phB[2] = {0, 0};
            for (int kc = 0; kc < 16; kc++) {
                const int b = kc & 1;
                mbar_wait(fA[b], phA[b] & 1); phA[b]++;
                mbar_wait(fB[b], phB[b] & 1); phB[b]++;
                uint64_t ad = mkdesc(abase + b * 16384);
                #pragma unroll
                for (int l = 0; l < 2; l++) {
                    uint64_t bd = mkdesc(bbase + b * 32768 + l * 16384);
                    #pragma unroll
                    for (int ks = 0; ks < 4; ks++)
                        mma_tf32_ss(tmem + l * 128, ad + ks * 2, bd + ks * 2,
                                    !(kc == 0 && ks == 0));
                }
                tc_commit(kc == 15 ? mbF : eAB[b]);
            }
        }
    }

    // ---- epilogue: D1[128,256] + b1, relu, cvt, swizzled h1 chunks ----
    mbar_wait(mbF, 0);
    tc_fence_after();
    {
        const int sp  = warp & 3;
        const int r   = sp * 32 + lane;
        const int cb0 = (warp >> 2) * 128;      // local col base (0 or 128)
        #pragma unroll
        for (int g = 0; g < 4; g++) {
            const int col  = cb0 + g * 32;      // local col in [0,256)
            const int gcol = half * 256 + col;  // global h1 col
            uint32_t regs[32];
            ldtm_x32(regs, tmem + col);
            tc_wait_ld();
            uint32_t* blk = h1img + ((size_t)tile * 16 + (gcol >> 5)) * 4096;
            #pragma unroll
            for (int q = 0; q < 8; q++) {
                float4 bv = *reinterpret_cast<const float4*>(b1 + gcol + q * 4);
                uint4 t;
                t.x = f2tf32(fmaxf(__uint_as_float(regs[q*4+0]) + bv.x, 0.f));
                t.y = f2tf32(fmaxf(__uint_as_float(regs[q*4+1]) + bv.y, 0.f));
                t.z = f2tf32(fmaxf(__uint_as_float(regs[q*4+2]) + bv.z, 0.f));
                t.w = f2tf32(fmaxf(__uint_as_float(regs[q*4+3]) + bv.w, 0.f));
                *reinterpret_cast<uint4*>(blk + (SWZ(r * 128 + q * 16) >> 2)) = t;
            }
        }
    }
    __syncthreads();
    if (warp == 0) tc_dealloc(tmem, 256);
#endif
}

// ---------------------------------------------------------------------------
// GEMM2+3 fused: 384 threads, 8 evac warps, producer = warp 8.
// ---------------------------------------------------------------------------
__global__ __launch_bounds__(384)
void gemm23_kernel(const uint32_t* __restrict__ h1img,
                   const uint32_t* __restrict__ w2img,
                   const float* __restrict__ b2,
                   const uint32_t* __restrict__ w3img,
                   const float* __restrict__ bs3,
                   float* __restrict__ out, int M)
{
#if TC_OK
    extern __shared__ char dynraw[];
    __shared__ uint32_t s_tptr[1];
    __shared__ alignas(8) uint64_t s_bars[11];

    const int tid  = threadIdx.x;
    const int warp = tid >> 5;
    const int lane = tid & 31;
    const int tile = blockIdx.x;
    const int row0 = tile * 128;

    uint32_t dbase = (smem_u32(dynraw) + 1023u) & ~1023u;
    char* dyn = dynraw + (dbase - smem_u32(dynraw));
    const uint32_t abase = dbase;                 // A2 ring 2x16KB; A3 4x16KB
    const uint32_t bbase = dbase + 65536;         // B2 ring 2x64KB; B3 ring 2x64KB

    if (warp == 0) tc_alloc(smem_u32(s_tptr), 512);
    if (tid == 0) {
        for (int i = 0; i < 11; i++) mbar_init(smem_u32(&s_bars[i]), 1);
    }
    __syncthreads();
    const uint32_t tmem = s_tptr[0];
    const uint32_t fA[2]  = { smem_u32(&s_bars[0]), smem_u32(&s_bars[1]) };
    const uint32_t fB[2]  = { smem_u32(&s_bars[2]), smem_u32(&s_bars[3]) };
    const uint32_t eAB[2] = { smem_u32(&s_bars[4]), smem_u32(&s_bars[5]) };
    const uint32_t mbF2   = smem_u32(&s_bars[6]);
    const uint32_t fB3[2] = { smem_u32(&s_bars[7]), smem_u32(&s_bars[8]) };
    const uint32_t eG3    = smem_u32(&s_bars[9]);
    const uint32_t mbF3   = smem_u32(&s_bars[10]);

    if (warp == 8) {
        if (elect1()) {
            int ph[2] = {0, 0};
            for (int kc = 0; kc < 16; kc++) {
                const int b = kc & 1;
                if (kc >= 2) { mbar_wait(eAB[b], ph[b] & 1); ph[b]++; }
                mbar_expect_tx(fA[b], 16384);
                bulk_g2s(abase + b * 16384,
                         h1img + ((size_t)tile * 16 + kc) * 4096, 16384, fA[b]);
                mbar_expect_tx(fB[b], 65536);
                #pragma unroll
                for (int nt = 0; nt < 4; nt++)
                    bulk_g2s(bbase + b * 65536 + nt * 16384,
                             w2img + (size_t)(nt * 16 + kc) * 4096, 16384, fB[b]);
            }
            mbar_wait(mbF2, 0);
            int phg = 0;
            for (int g = 0; g < 4; g++) {
                const int s = g & 1;
                if (g >= 2) { mbar_wait(eG3, phg & 1); phg++; }
                mbar_expect_tx(fB3[s], 65536);
                bulk_g2s(bbase + s * 65536, w3img + (size_t)g * 16384, 65536, fB3[s]);
            }
        }
    }

    if (warp == 0) {
        if (elect1()) {
            int phA[2] = {0, 0}, phB[2] = {0, 0};
            for (int kc = 0; kc < 16; kc++) {
                const int b = kc & 1;
                mbar_wait(fA[b], phA[b] & 1); phA[b]++;
                mbar_wait(fB[b], phB[b] & 1); phB[b]++;
                uint64_t ad = mkdesc(abase + b * 16384);
                #pragma unroll
                for (int nt = 0; nt < 4; nt++) {
                    uint64_t bd = mkdesc(bbase + b * 65536 + nt * 16384);
                    #pragma unroll
                    for (int ks = 0; ks < 4; ks++)
                        mma_tf32_ss(tmem + nt * 128, ad + ks * 2, bd + ks * 2,
                                    !(kc == 0 && ks == 0));
                }
                tc_commit(kc == 15 ? mbF2 : eAB[b]);
            }
        }
    }

    if (warp < 8) {
        mbar_wait(mbF2, 0);
        tc_fence_after();
        const int r  = (warp & 3) * 32 + lane;
        const int jh = (warp >> 2) * 2;
        int phb3[2] = {0, 0};
        for (int g = 0; g < 4; g++) {
            if (g >= 1) mbar_wait(eG3, (g - 1) & 1);
            #pragma unroll
            for (int jj = 0; jj < 2; jj++) {
                const int j = jh + jj;
                uint32_t regs[32];
                ldtm_x32(regs, tmem + g * 128 + j * 32);
                tc_wait_ld();
                const int colb = g * 128 + j * 32;
                #pragma unroll
                for (int q = 0; q < 8; q++) {
                    float4 bv = *reinterpret_cast<const float4*>(b2 + colb + q * 4);
                    uint4 t;
                    t.x = f2tf32(fmaxf(__uint_as_float(regs[q*4+0]) + bv.x, 0.f));
                    t.y = f2tf32(fmaxf(__uint_as_float(regs[q*4+1]) + bv.y, 0.f));
                    t.z = f2tf32(fmaxf(__uint_as_float(regs[q*4+2]) + bv.z, 0.f));
                    t.w = f2tf32(fmaxf(__uint_as_float(regs[q*4+3]) + bv.w, 0.f));
                    *reinterpret_cast<uint4*>(
                        dyn + j * 16384 + SWZ(r * 128 + q * 16)) = t;
                }
            }
            fence_async_shared();
            asm volatile("bar.sync 1, 256;" ::: "memory");
            if (warp == 0 && elect1()) {
                const int s = g & 1;
                mbar_wait(fB3[s], phb3[s] & 1); phb3[s]++;
                #pragma unroll
                for (int j = 0; j < 4; j++) {
                    uint64_t ad = mkdesc(abase + j * 16384);
                    uint64_t bd = mkdesc(bbase + s * 65536 + j * 16384);
                    #pragma unroll
                    for (int ks = 0; ks < 4; ks++)
                        mma_tf32_ss(tmem, ad + ks * 2, bd + ks * 2,
                                    !(g == 0 && j == 0 && ks == 0));
                }
                tc_commit(g == 3 ? mbF3 : eG3);
            }
        }
    }

    mbar_wait(mbF3, 0);
    tc_fence_after();
    if (warp < 8) {
        const int sp  = warp & 3;
        const int row = row0 + sp * 32 + lane;
        const int cb0 = (warp >> 2) * 64;
        #pragma unroll
        for (int gg = 0; gg < 2; gg++) {
            const int col = cb0 + gg * 32;
            uint32_t regs[32];
            ldtm_x32(regs, tmem + col);
            tc_wait_ld();
            if (row < M) {
                #pragma unroll
                for (int q = 0; q < 8; q++) {
                    float4 bv = *reinterpret_cast<const float4*>(bs3 + col + q * 4);
                    float4 o;
                    o.x = __uint_as_float(regs[q*4+0]) + bv.x;
                    o.y = __uint_as_float(regs[q*4+1]) + bv.y;
                    o.z = __uint_as_float(regs[q*4+2]) + bv.z;
                    o.w = __uint_as_float(regs[q*4+3]) + bv.w;
                    *reinterpret_cast<float4*>(out + (size_t)row * 128 + col + q * 4) = o;
                }
            }
        }
    }
    __syncthreads();
    if (warp == 0) tc_dealloc(tmem, 512);
#endif
}

// ---------------------------------------------------------------------------
extern "C" void kernel_launch(void* const* d_in, const int* in_sizes, int n_in,
                              void* d_out, int out_size)
{
    const float* src   = (const float*)d_in[0];
    const float* dstv  = (const float*)d_in[1];
    const float* eat   = (const float*)d_in[2];
    const float* u     = (const float*)d_in[3];
    const int*   batch = (const int*)  d_in[4];
    const float* W1    = (const float*)d_in[5];
    const float* b1    = (const float*)d_in[6];
    const float* W2    = (const float*)d_in[7];
    const float* b2    = (const float*)d_in[8];
    const float* W3    = (const float*)d_in[9];
    const float* b3    = (const float*)d_in[10];
    float*       out   = (float*)d_out;

    const int M = in_sizes[4];

    uint32_t *xi, *h1i, *w1i, *w2i, *w3i;
    cudaGetSymbolAddress((void**)&xi,  g_xi);
    cudaGetSymbolAddress((void**)&h1i, g_h1i);
    cudaGetSymbolAddress((void**)&w1i, g_w1i);
    cudaGetSymbolAddress((void**)&w2i, g_w2i);
    cudaGetSymbolAddress((void**)&w3i, g_w3i);

    static bool attr_done = false;
    if (!attr_done) {
        // gemm1: A 2x16K + B 2x32K = 96K + 1K pad -> 98K; 2 CTAs/SM = 196K OK
        cudaFuncSetAttribute(gemm1_bulk,
            cudaFuncAttributeMaxDynamicSharedMemorySize, 100352);
        cudaFuncSetAttribute(gemm23_kernel,
            cudaFuncAttributeMaxDynamicSharedMemorySize, 197632);
        attr_done = true;
    }

    prep_weights<<<(512 * 512 + 255) / 256, 256>>>(W1, w1i, 512);
    prep_weights<<<(512 * 512 + 255) / 256, 256>>>(W2, w2i, 512);
    prep_weights<<<(512 * 128 + 255) / 256, 256>>>(W3, w3i, 128);

    const int tiles = (M + 127) / 128;

    dim3 gg(tiles, 16);
    gather_kernel<<<gg, 256>>>(src, dstv, eat, u, batch, xi, M);

    dim3 g1(tiles, 2);
    gemm1_bulk<<<g1, 256, 100352>>>(xi, w1i, b1, h1i, M);

    gemm23_kernel<<<tiles, 384, 197632>>>(h1i, w2i, b2, w3i, b3, out, M);
}